// round 11
// baseline (speedup 1.0000x reference)
#include <cuda_runtime.h>
#include <cstdint>
#include <math.h>

#define BATCH 2048
#define TT 64
#define EE 256
#define SCALE 0.125f
#define FK  16384
#define SPLITK 9            // uneven: 8 x 1824 + 1 x 1792

// ------------------------------------------------------------------
// scratch (static __device__ — no allocations allowed)
// ------------------------------------------------------------------
__device__ float g_x[BATCH * TT * EE];              // attn + query (134MB)
__device__ float g_partial[SPLITK * BATCH * 256];   // 18.9MB

// ------------------------------------------------------------------
// packed f32x2 helpers (FFMA2 — only reachable via PTX fma.rn.f32x2)
// ------------------------------------------------------------------
__device__ __forceinline__ void ffma2(uint64_t& d, uint64_t a, uint64_t b) {
    asm("fma.rn.f32x2 %0, %1, %2, %0;" : "+l"(d) : "l"(a), "l"(b));
}
__device__ __forceinline__ uint64_t dupf(float x) {
    uint64_t d; asm("mov.b64 %0, {%1, %1};" : "=l"(d) : "f"(x)); return d;
}
__device__ __forceinline__ void unpack2(uint64_t d, float& lo, float& hi) {
    asm("mov.b64 {%0, %1}, %2;" : "=f"(lo), "=f"(hi) : "l"(d));
}
__device__ __forceinline__ uint32_t smem_u32(const void* p) {
    uint32_t a;
    asm("{ .reg .u64 t; cvta.to.shared.u64 t, %1; cvt.u32.u64 %0, t; }" : "=r"(a) : "l"(p));
    return a;
}
#define CP_ASYNC16(dst, src) \
    asm volatile("cp.async.cg.shared.global [%0], [%1], 16;" :: "r"(dst), "l"(src) : "memory")
#define CP_COMMIT() \
    asm volatile("cp.async.commit_group;" ::: "memory")
#define CP_WAIT(n) \
    asm volatile("cp.async.wait_group %0;" :: "n"(n) : "memory")

// ------------------------------------------------------------------
// attention kernel: 256 threads, 2 CTAs/SM.
// S-phase: acc packed over q (pairs come pre-packed from smem);
//          only 2 k-scalars per e need dup-MOVs.
// ------------------------------------------------------------------
#define EC 64
#define NEC 4
#define KC 16
#define NKC 4
#define S_PITCH 65

#define OFF_QT 0
#define OFF_KT 8192
#define OFF_SS 16384
#define OFF_V  0
#define ATTN_SMEM_BYTES ((16384 + 4160) * 4)

__device__ __forceinline__ int qsw(int el, int q) {
    return el * 64 + ((((q) >> 2) ^ (el & 15)) << 2) + (q & 3);
}

__global__ __launch_bounds__(256, 2)
void attn_kernel(const float* __restrict__ Qg, const float* __restrict__ Kg,
                 const float* __restrict__ Vg, float* __restrict__ Ag)
{
    extern __shared__ float sm[];
    float* QT = sm + OFF_QT;
    float* KT = sm + OFF_KT;
    float* Ss = sm + OFF_SS;
    float* Vc = sm + OFF_V;

    const int tid = threadIdx.x;
    const int b   = blockIdx.x;
    const size_t base = (size_t)b * TT * EE;
    const float* qb = Qg + base;
    const float* kb = Kg + base;
    const float* vb = Vg + base;

    const int el = tid & 63;
    const int h  = tid >> 6;
    const int tx = tid & 15;
    const int ty = tid >> 4;

    {
        const float* qsrc = qb + (h * 16) * EE + el;
        const float* ksrc = kb + (h * 16) * EE + el;
        float qs[16], ks[16];
        #pragma unroll
        for (int r = 0; r < 16; ++r) {
            qs[r] = qsrc[r * EE];
            ks[r] = ksrc[r * EE];
        }
        #pragma unroll
        for (int r = 0; r < 16; ++r) {
            const int q = h * 16 + r;
            QT[qsw(el, q)] = qs[r];
            KT[qsw(el, q)] = ks[r];
        }
    }

    // ---- S = Q @ K^T : 8q (warp-uniform, pre-packed pairs) x 2k ----
    const int w = tid >> 5;     // warp: q rows w*8..w*8+7
    const int t = tid & 31;     // lane: k cols 2t, 2t+1

    uint64_t accS[4][2];        // [q-pair j][kk]
    #pragma unroll
    for (int j = 0; j < 4; ++j) { accS[j][0] = 0ull; accS[j][1] = 0ull; }

    int cur = 0;
    float qs[16], ks[16];
    for (int ec = 0; ec < NEC; ++ec) {
        __syncthreads();
        if (ec < NEC - 1) {
            const float* qsrc = qb + (h * 16) * EE + (ec + 1) * EC + el;
            const float* ksrc = kb + (h * 16) * EE + (ec + 1) * EC + el;
            #pragma unroll
            for (int r = 0; r < 16; ++r) {
                qs[r] = qsrc[r * EE];
                ks[r] = ksrc[r * EE];
            }
        }
        const float* Qb = QT + cur * 4096;
        const float* Kb = KT + cur * 4096;
        const int kblk = t >> 1;            // k block index (q>>2 analog)
        const int koff = 2 * (t & 1);       // offset within block
        #pragma unroll 16
        for (int e = 0; e < EC; ++e) {      // swizzle folds to immediates
            const int sw = e & 15;
            // q rows 8w..8w+7: blocks 2w and 2w+1, swizzled
            float4 qlo = *(const float4*)&Qb[e * 64 + (((2 * w)     ^ sw) << 2)];
            float4 qhi = *(const float4*)&Qb[e * 64 + (((2 * w + 1) ^ sw) << 2)];
            const uint64_t* ql = (const uint64_t*)&qlo;
            const uint64_t* qh = (const uint64_t*)&qhi;
            // k scalars 2t, 2t+1
            const float* kp = &Kb[e * 64 + ((kblk ^ sw) << 2) + koff];
            uint64_t k0 = dupf(kp[0]);
            uint64_t k1 = dupf(kp[1]);
            ffma2(accS[0][0], ql[0], k0);
            ffma2(accS[0][1], ql[0], k1);
            ffma2(accS[1][0], ql[1], k0);
            ffma2(accS[1][1], ql[1], k1);
            ffma2(accS[2][0], qh[0], k0);
            ffma2(accS[2][1], qh[0], k1);
            ffma2(accS[3][0], qh[1], k0);
            ffma2(accS[3][1], qh[1], k1);
        }
        if (ec < NEC - 1) {
            float* Qn = QT + (cur ^ 1) * 4096;
            float* Kn = KT + (cur ^ 1) * 4096;
            #pragma unroll
            for (int r = 0; r < 16; ++r) {
                const int q = h * 16 + r;
                Qn[qsw(el, q)] = qs[r];
                Kn[qsw(el, q)] = ks[r];
            }
            cur ^= 1;
        }
    }

    // store S (acc packed over q -> scalar scatter; one-time)
    #pragma unroll
    for (int j = 0; j < 4; ++j) {
        #pragma unroll
        for (int kk = 0; kk < 2; ++kk) {
            float lo, hi;
            unpack2(accS[j][kk], lo, hi);
            Ss[(w * 8 + 2 * j)     * S_PITCH + 2 * t + kk] = lo;
            Ss[(w * 8 + 2 * j + 1) * S_PITCH + 2 * t + kk] = hi;
        }
    }
    __syncthreads();

    const uint32_t vsm = smem_u32(Vc);
    #pragma unroll
    for (int j = 0; j < 4; ++j) {
        const int f4 = j * 256 + tid;
        CP_ASYNC16(vsm + f4 * 16, (const float4*)vb + f4);
    }
    CP_COMMIT();

    const int warp = tid >> 5, lane = tid & 31;
    #pragma unroll
    for (int rr = 0; rr < 8; ++rr) {
        const int r = warp * 8 + rr;
        float v1 = Ss[r * S_PITCH + lane]      * SCALE;
        float v2 = Ss[r * S_PITCH + lane + 32] * SCALE;
        float m = fmaxf(v1, v2);
        #pragma unroll
        for (int o = 16; o > 0; o >>= 1)
            m = fmaxf(m, __shfl_xor_sync(0xffffffffu, m, o));
        float e1 = expf(v1 - m);
        float e2 = expf(v2 - m);
        float s = e1 + e2;
        #pragma unroll
        for (int o = 16; o > 0; o >>= 1)
            s += __shfl_xor_sync(0xffffffffu, s, o);
        float inv = 1.0f / s;
        Ss[r * S_PITCH + lane]      = e1 * inv;
        Ss[r * S_PITCH + lane + 32] = e2 * inv;
    }

    uint64_t accA[4][4][2];
    #pragma unroll
    for (int i = 0; i < 4; ++i)
        #pragma unroll
        for (int eb = 0; eb < 4; ++eb) { accA[i][eb][0] = 0ull; accA[i][eb][1] = 0ull; }

    for (int kc = 0; kc < NKC; ++kc) {
        if (kc < NKC - 1) {
            const uint32_t dst = vsm + (((kc + 1) & 1) * 4096) * 4;
            #pragma unroll
            for (int j = 0; j < 4; ++j) {
                const int f4 = j * 256 + tid;
                CP_ASYNC16(dst + f4 * 16, (const float4*)vb + (kc + 1) * 1024 + f4);
            }
            CP_COMMIT();
            CP_WAIT(1);
        } else {
            CP_WAIT(0);
        }
        __syncthreads();
        const float* Vb = Vc + (kc & 1) * 4096;
        #pragma unroll 2
        for (int kl = 0; kl < KC; ++kl) {
            const int kg = kc * KC + kl;
            float4 v0 = *(const float4*)&Vb[kl * 256 + tx * 4];
            float4 v1 = *(const float4*)&Vb[kl * 256 + 64 + tx * 4];
            float4 v2 = *(const float4*)&Vb[kl * 256 + 128 + tx * 4];
            float4 v3 = *(const float4*)&Vb[kl * 256 + 192 + tx * 4];
            uint64_t vp[4][2];
            { const uint64_t* u = (const uint64_t*)&v0; vp[0][0] = u[0]; vp[0][1] = u[1]; }
            { const uint64_t* u = (const uint64_t*)&v1; vp[1][0] = u[0]; vp[1][1] = u[1]; }
            { const uint64_t* u = (const uint64_t*)&v2; vp[2][0] = u[0]; vp[2][1] = u[1]; }
            { const uint64_t* u = (const uint64_t*)&v3; vp[3][0] = u[0]; vp[3][1] = u[1]; }
            #pragma unroll
            for (int i = 0; i < 4; ++i) {
                uint64_t sd = dupf(Ss[(ty * 4 + i) * S_PITCH + kg]);
                #pragma unroll
                for (int eb = 0; eb < 4; ++eb) {
                    ffma2(accA[i][eb][0], sd, vp[eb][0]);
                    ffma2(accA[i][eb][1], sd, vp[eb][1]);
                }
            }
        }
        __syncthreads();
    }

    float* ab = Ag + base;
    float* xb = g_x + base;
    #pragma unroll
    for (int i = 0; i < 4; ++i) {
        const int qrow = ty * 4 + i;
        #pragma unroll
        for (int eb = 0; eb < 4; ++eb) {
            const int e0 = eb * 64 + tx * 4;
            float4 o;
            unpack2(accA[i][eb][0], o.x, o.y);
            unpack2(accA[i][eb][1], o.z, o.w);
            float4 q = *(const float4*)&qb[qrow * EE + e0];
            float4 x = make_float4(o.x + q.x, o.y + q.y, o.z + q.z, o.w + q.w);
            *(float4*)&ab[qrow * EE + e0] = o;
            *(float4*)&xb[qrow * EE + e0] = x;
        }
    }
}

// ------------------------------------------------------------------
// FF GEMM: partial[s][m][n] = g_x[m, s-range] @ W^T   (FFMA2 SIMT)
// 256 threads, BM=128 BN=128 BK=32, 8m x 8n, acc packed over n.
// Single __syncthreads per tile (compute(buf), then STS into buf^1).
// grid (16, 2, 9): 288 CTAs, uneven k-splits.
// ------------------------------------------------------------------
#define FBM 128
#define FBN 128
#define FBK 32
#define XP 132
#define TILE_WORDS (FBK * XP)        // 4224
#define FF_SMEM_BYTES (4 * TILE_WORDS * 4)   // 67584 B
#define KTPS 57                      // splits 0..7: 57 tiles; split 8: 56

__global__ __launch_bounds__(256, 2)
void ff2_kernel(const float* __restrict__ Wg)
{
    extern __shared__ float fsm[];
    float* Xs = fsm;                         // [2][32][132]
    float* Ws = fsm + 2 * TILE_WORDS;        // [2][32][132]

    const int tid = threadIdx.x;
    const int m0 = blockIdx.x * FBM;
    const int n0 = blockIdx.y * FBN;
    const int z  = blockIdx.z;
    const size_t kbase = (size_t)z * (KTPS * FBK);
    const int ntile = (z == SPLITK - 1) ? 56 : KTPS;

    const int lrow = tid >> 2;
    const int lc   = (tid & 3) * 4;
    const float* xp0 = g_x + (size_t)(m0 + lrow) * FK + kbase + lc;
    const float* xp1 = g_x + (size_t)(m0 + 64 + lrow) * FK + kbase + lc;
    const float* wp0 = Wg  + (size_t)(n0 + lrow) * FK + kbase + lc;
    const float* wp1 = Wg  + (size_t)(n0 + 64 + lrow) * FK + kbase + lc;

    const int tx = tid & 15;
    const int ty = tid >> 4;

    uint64_t acc[8][4];
    #pragma unroll
    for (int m = 0; m < 8; ++m)
        #pragma unroll
        for (int p = 0; p < 4; ++p) acc[m][p] = 0ull;

    // prologue: load tile 0, commit to buf 0, one sync
    float4 xA0 = *(const float4*)xp0,  xA1 = *(const float4*)(xp0 + 16);
    float4 xB0 = *(const float4*)xp1,  xB1 = *(const float4*)(xp1 + 16);
    float4 wA0 = *(const float4*)wp0,  wA1 = *(const float4*)(wp0 + 16);
    float4 wB0 = *(const float4*)wp1,  wB1 = *(const float4*)(wp1 + 16);
    {
        const float* a0 = (const float*)&xA0; const float* a1 = (const float*)&xA1;
        const float* b0 = (const float*)&xB0; const float* b1 = (const float*)&xB1;
        const float* c0 = (const float*)&wA0; const float* c1 = (const float*)&wA1;
        const float* d0 = (const float*)&wB0; const float* d1 = (const float*)&wB1;
        #pragma unroll
        for (int j = 0; j < 4; ++j) {
            Xs[(lc + j) * XP + lrow]           = a0[j];
            Xs[(lc + 16 + j) * XP + lrow]      = a1[j];
            Xs[(lc + j) * XP + lrow + 64]      = b0[j];
            Xs[(lc + 16 + j) * XP + lrow + 64] = b1[j];
            Ws[(lc + j) * XP + lrow]           = c0[j];
            Ws[(lc + 16 + j) * XP + lrow]      = c1[j];
            Ws[(lc + j) * XP + lrow + 64]      = d0[j];
            Ws[(lc + 16 + j) * XP + lrow + 64] = d1[j];
        }
    }
    __syncthreads();

    for (int t = 0; t < ntile; ++t) {
        const int buf = t & 1;
        float* Xb = Xs + buf * TILE_WORDS;
        float* Wb = Ws + buf * TILE_WORDS;

        const bool more = (t + 1 < ntile);
        if (more) {    // prefetch next tile into regs (consumed after compute)
            const size_t kt = (size_t)(t + 1) * FBK;
            xA0 = *(const float4*)(xp0 + kt);  xA1 = *(const float4*)(xp0 + kt + 16);
            xB0 = *(const float4*)(xp1 + kt);  xB1 = *(const float4*)(xp1 + kt + 16);
            wA0 = *(const float4*)(wp0 + kt);  wA1 = *(const float4*)(wp0 + kt + 16);
            wB0 = *(const float4*)(wp1 + kt);  wB1 = *(const float4*)(wp1 + kt + 16);
        }

        #pragma unroll
        for (int k = 0; k < FBK; ++k) {
            const float* xr = Xb + k * XP + ty * 8;
            float4 a0 = *(const float4*)xr;
            float4 a1 = *(const float4*)(xr + 4);
            const float* wr = Wb + k * XP + tx * 8;
            float4 b0 = *(const float4*)wr;
            float4 b1 = *(const float4*)(wr + 4);
            uint64_t bp[4];
            { const uint64_t* u = (const uint64_t*)&b0; bp[0] = u[0]; bp[1] = u[1]; }
            { const uint64_t* u = (const uint64_t*)&b1; bp[2] = u[0]; bp[3] = u[1]; }
            const float aa[8] = {a0.x, a0.y, a0.z, a0.w, a1.x, a1.y, a1.z, a1.w};
            #pragma unroll
            for (int m = 0; m < 8; ++m) {
                uint64_t ad = dupf(aa[m]);
                #pragma unroll
                for (int p = 0; p < 4; ++p) ffma2(acc[m][p], ad, bp[p]);
            }
        }

        if (more) {    // commit prefetched tile to the other buffer
            float* Xn = Xs + (buf ^ 1) * TILE_WORDS;
            float* Wn = Ws + (buf ^ 1) * TILE_WORDS;
            const float* a0 = (const float*)&xA0; const float* a1 = (const float*)&xA1;
            const float* b0 = (const float*)&xB0; const float* b1 = (const float*)&xB1;
            const float* c0 = (const float*)&wA0; const float* c1 = (const float*)&wA1;
            const float* d0 = (const float*)&wB0; const float* d1 = (const float*)&wB1;
            #pragma unroll
            for (int j = 0; j < 4; ++j) {
                Xn[(lc + j) * XP + lrow]           = a0[j];
                Xn[(lc + 16 + j) * XP + lrow]      = a1[j];
                Xn[(lc + j) * XP + lrow + 64]      = b0[j];
                Xn[(lc + 16 + j) * XP + lrow + 64] = b1[j];
                Wn[(lc + j) * XP + lrow]           = c0[j];
                Wn[(lc + 16 + j) * XP + lrow]      = c1[j];
                Wn[(lc + j) * XP + lrow + 64]      = d0[j];
                Wn[(lc + 16 + j) * XP + lrow + 64] = d1[j];
            }
        }
        __syncthreads();
    }

    #pragma unroll
    for (int m = 0; m < 8; ++m) {
        float c[8];
        #pragma unroll
        for (int p = 0; p < 4; ++p) unpack2(acc[m][p], c[2 * p], c[2 * p + 1]);
        float* pr = g_partial + ((size_t)z * BATCH + m0 + ty * 8 + m) * 256
                    + n0 + tx * 8;
        *(float4*)pr       = make_float4(c[0], c[1], c[2], c[3]);
        *(float4*)(pr + 4) = make_float4(c[4], c[5], c[6], c[7]);
    }
}

// ------------------------------------------------------------------
// reduce: out = relu(sum_s partial + bias)
// ------------------------------------------------------------------
__global__ __launch_bounds__(256)
void reduce_kernel(const float* __restrict__ bias, float* __restrict__ out)
{
    const int g = blockIdx.x * 256 + threadIdx.x;
    const int m = g >> 6;
    const int nc = g & 63;
    float4 acc = ((const float4*)bias)[nc];
    #pragma unroll
    for (int ks = 0; ks < SPLITK; ++ks) {
        float4 p = ((const float4*)g_partial)[((size_t)ks * BATCH + m) * 64 + nc];
        acc.x += p.x; acc.y += p.y; acc.z += p.z; acc.w += p.w;
    }
    acc.x = fmaxf(acc.x, 0.0f); acc.y = fmaxf(acc.y, 0.0f);
    acc.z = fmaxf(acc.z, 0.0f); acc.w = fmaxf(acc.w, 0.0f);
    ((float4*)out)[(size_t)m * 64 + nc] = acc;
}

// ------------------------------------------------------------------
// launch
// ------------------------------------------------------------------
extern "C" void kernel_launch(void* const* d_in, const int* in_sizes, int n_in,
                              void* d_out, int out_size)
{
    const float* value = (const float*)d_in[0];
    const float* key_  = (const float*)d_in[1];
    const float* query = (const float*)d_in[2];
    const float* W_ff  = (const float*)d_in[4];
    const float* b_ff  = (const float*)d_in[5];

    float* out  = (float*)d_out;                 // [2048, 256]
    float* attn = out + (size_t)BATCH * 256;     // [2048, 64, 256]

    cudaFuncSetAttribute(attn_kernel,
                         cudaFuncAttributeMaxDynamicSharedMemorySize, ATTN_SMEM_BYTES);
    cudaFuncSetAttribute(ff2_kernel,
                         cudaFuncAttributeMaxDynamicSharedMemorySize, FF_SMEM_BYTES);

    attn_kernel<<<BATCH, 256, ATTN_SMEM_BYTES>>>(query, key_, value, attn);
    ff2_kernel<<<dim3(16, 2, SPLITK), 256, FF_SMEM_BYTES>>>(W_ff);
    reduce_kernel<<<512, 256>>>(b_ff, out);
}